// round 15
// baseline (speedup 1.0000x reference)
#include <cuda_runtime.h>
#include <cstdint>

// Problem constants
#define CB 2
#define CS 2048
#define CD 1024
#define CH 16
#define CHD 64
#define CM (CB*CS)   // 4096 tokens

// Scratch (allocation-free rule: __device__ globals; referenced ONLY in device code)
__device__ float g_q[(size_t)CM * CD];        // q activations (fp32)
__device__ float g_kvh[(size_t)CM * 128];     // hi tf32 of [k_sum | v_sum]
__device__ float g_kvl[(size_t)CM * 128];     // lo tf32
__device__ float g_xh[(size_t)CM * CD];       // x pre-split
__device__ float g_xl[(size_t)CM * CD];
__device__ float g_aoh[(size_t)CM * CD];      // attention out pre-split
__device__ float g_aol[(size_t)CM * CD];
__device__ float g_W0h[1152 * CD];            // combined [Wq ; Wkv_sum] pre-split
__device__ float g_W0l[1152 * CD];
__device__ float g_b0[1152];
__device__ float g_Woh[CD * CD];              // Wout pre-split
__device__ float g_Wol[CD * CD];
__device__ float g_Wkv[128 * CD];             // head-summed K/V weights (raw)
__device__ float g_bkv[128];

// ---------------------------------------------------------------------------
// helpers
// ---------------------------------------------------------------------------
__device__ __forceinline__ uint32_t smem_u32(const void* p) {
    uint32_t a;
    asm("{ .reg .u64 t; cvta.to.shared.u64 t, %1; cvt.u32.u64 %0, t; }"
        : "=r"(a) : "l"(p));
    return a;
}
__device__ __forceinline__ float tf32_rna(float x) {
    uint32_t r;
    asm("cvt.rna.tf32.f32 %0, %1;" : "=r"(r) : "f"(x));
    return __uint_as_float(r);
}
__device__ __forceinline__ void split_tf32(float x, uint32_t& h, uint32_t& l) {
    float hf = tf32_rna(x);
    h = __float_as_uint(hf);
    l = __float_as_uint(tf32_rna(x - hf));
}
__device__ __forceinline__ void mma8(float* c, const uint32_t* a, const uint32_t* b) {
    asm volatile(
        "mma.sync.aligned.m16n8k8.row.col.f32.tf32.tf32.f32 "
        "{%0,%1,%2,%3}, {%4,%5,%6,%7}, {%8,%9}, {%0,%1,%2,%3};"
        : "+f"(c[0]), "+f"(c[1]), "+f"(c[2]), "+f"(c[3])
        : "r"(a[0]), "r"(a[1]), "r"(a[2]), "r"(a[3]), "r"(b[0]), "r"(b[1]));
}
__device__ __forceinline__ void cp16(uint32_t dst, const float* src) {
    asm volatile("cp.async.cg.shared.global [%0], [%1], 16;"
                 :: "r"(dst), "l"(src) : "memory");
}
#define CP_COMMIT() asm volatile("cp.async.commit_group;" ::: "memory")
#define CP_WAIT(n)  asm volatile("cp.async.wait_group %0;" :: "n"(n) : "memory")

// ---------------------------------------------------------------------------
// prep kernels (elementwise, a few us total)
// ---------------------------------------------------------------------------
__global__ __launch_bounds__(256) void prep_k(const float* __restrict__ Wqkv,
                                              const float* __restrict__ bqkv)
{
    int idx = blockIdx.x * 256 + threadIdx.x;
    if (idx < 128 * 1024) {
        int r = idx >> 10;
        int c = idx & 1023;
        int rr = r & 63;
        int base = (r < 64 ? 1024 : 2048) + rr;
        float sum = 0.f;
        #pragma unroll
        for (int h = 0; h < 16; h++)
            sum += Wqkv[(size_t)(base + h * 64) * CD + c];
        g_Wkv[(size_t)r * CD + c] = sum;
    }
    if (idx < 128) {
        int rr = idx & 63;
        int base = (idx < 64 ? 1024 : 2048) + rr;
        float s = 0.f;
        #pragma unroll
        for (int h = 0; h < 16; h++)
            s += bqkv[base + h * 64];
        g_bkv[idx] = s;
    }
}

__global__ __launch_bounds__(256) void prep_split_x(const float* __restrict__ x)
{
    int idx = blockIdx.x * 256 + threadIdx.x;   // 4M elements
    float v = x[idx];
    float h = tf32_rna(v);
    g_xh[idx] = h;
    g_xl[idx] = tf32_rna(v - h);
}

__global__ __launch_bounds__(256) void prep_W0(const float* __restrict__ Wqkv,
                                               const float* __restrict__ bqkv)
{
    int idx = blockIdx.x * 256 + threadIdx.x;   // 1152*1024
    int r = idx >> 10;
    int c = idx & 1023;
    float v = (r < 1024) ? Wqkv[(size_t)r * CD + c] : g_Wkv[(size_t)(r - 1024) * CD + c];
    float h = tf32_rna(v);
    g_W0h[idx] = h;
    g_W0l[idx] = tf32_rna(v - h);
    if (idx < 1152)
        g_b0[idx] = (idx < 1024) ? bqkv[idx] : g_bkv[idx - 1024];
}

__global__ __launch_bounds__(256) void prep_Wout(const float* __restrict__ Wout)
{
    int idx = blockIdx.x * 256 + threadIdx.x;   // 1M elements
    float v = Wout[idx];
    float h = tf32_rna(v);
    g_Woh[idx] = h;
    g_Wol[idx] = tf32_rna(v - h);
}

// ---------------------------------------------------------------------------
// tf32 mma.sync GEMM (3xTF32), operands pre-split in global (selected from
// MODE *inside device code* — passing __device__ symbols from host was the
// R14 bug), cp.async double-buffered, BK=16, 2 CTAs/SM.
// Hazard proof: at iter kt we issue tile kt+1 into buf[(kt+1)&1] =
// buf[(kt-1)&1]; the iteration-entry __syncthreads() (a) orders that issue
// after every warp's mma reads of iter kt-1 on that same buffer. wait_group(1)
// leaves exactly tile kt complete (groups retire in order); sync (b) publishes.
// MODE 0: A=g_xh/l, B=g_W0h/l, bias=g_b0; C cols <1024 -> g_q; else kv split
// MODE 1: A=g_aoh/l, B=g_Woh/l, bias=arg;  C -> d_out
// ---------------------------------------------------------------------------
#define LDPA 20
#define APL (128 * LDPA)                 // floats per plane
#define GST (4 * APL)                    // 10240 floats per stage (40KB)
#define GEMM_SMEM_BYTES (2 * GST * 4)    // 81920

template<int MODE>
__global__ __launch_bounds__(256, 2) void gemm_cp(const float* __restrict__ bias_in,
                                                  float* __restrict__ Cout)
{
    extern __shared__ float sm[];
    const uint32_t sb = smem_u32(sm);

    const int tid = threadIdx.x;
    const int wid = tid >> 5;
    const int lane = tid & 31;
    const int grp = lane >> 2;
    const int q   = lane & 3;
    const int warp_m = wid >> 2;
    const int warp_n = wid & 3;

    const int n0 = blockIdx.x * 128;
    const int m0 = blockIdx.y * 128;

    // device-side symbol selection (the R14 fix)
    const float* AhG = (MODE == 0) ? g_xh  : g_aoh;
    const float* AlG = (MODE == 0) ? g_xl  : g_aol;
    const float* BhG = (MODE == 0) ? g_W0h : g_Woh;
    const float* BlG = (MODE == 0) ? g_W0l : g_Wol;
    const float* bias = (MODE == 0) ? g_b0 : bias_in;

    const float* srcp[4];
    srcp[0] = AhG + (size_t)m0 * CD;
    srcp[1] = AlG + (size_t)m0 * CD;
    srcp[2] = BhG + (size_t)n0 * CD;
    srcp[3] = BlG + (size_t)n0 * CD;
    const float* bp = bias + n0;

    float acc[4][4][4];
    #pragma unroll
    for (int mt = 0; mt < 4; mt++)
        #pragma unroll
        for (int nt = 0; nt < 4; nt++)
            #pragma unroll
            for (int r = 0; r < 4; r++) acc[mt][nt][r] = 0.f;

    // cp.async roles: 8 x 16B per thread per stage (4 planes x 128 x 16)
    #define ISSUE_TILE(kt_, stg_)                                              \
    do {                                                                       \
        const uint32_t sbase = sb + (uint32_t)(stg_) * GST * 4;                \
        const int kof = (kt_) * 16;                                            \
        _Pragma("unroll")                                                      \
        for (int i = 0; i < 8; i++) {                                          \
            const int f = tid + i * 256;                                       \
            const int pl = f >> 9;                                             \
            const int row = (f >> 2) & 127;                                    \
            const int c4 = (f & 3) << 2;                                       \
            cp16(sbase + (uint32_t)(pl * APL + row * LDPA + c4) * 4,           \
                 srcp[pl] + (size_t)row * CD + kof + c4);                      \
        }                                                                      \
        CP_COMMIT();                                                           \
    } while (0)

    ISSUE_TILE(0, 0);

    for (int kt = 0; kt < 64; kt++) {
        const int stg = kt & 1;
        const float* Ash = sm + stg * GST;
        const float* Asl = Ash + APL;
        const float* Bsh = Ash + 2 * APL;
        const float* Bsl = Ash + 3 * APL;

        if (kt > 0) __syncthreads();          // (a) buf[(kt+1)&1] consumption done
        if (kt < 63) { ISSUE_TILE(kt + 1, stg ^ 1); CP_WAIT(1); }
        else         { CP_WAIT(0); }
        __syncthreads();                      // (b) tile kt visible

        #pragma unroll
        for (int ks = 0; ks < 2; ks++) {
            const int k = ks * 8 + q;
            uint32_t ah[4][4], al[4][4], bh[4][2], bl[4][2];
            #pragma unroll
            for (int mt = 0; mt < 4; mt++) {
                const int mb = (warp_m * 64 + mt * 16 + grp) * LDPA;
                ah[mt][0] = __float_as_uint(Ash[mb + k]);
                ah[mt][1] = __float_as_uint(Ash[mb + 8 * LDPA + k]);
                ah[mt][2] = __float_as_uint(Ash[mb + k + 4]);
                ah[mt][3] = __float_as_uint(Ash[mb + 8 * LDPA + k + 4]);
                al[mt][0] = __float_as_uint(Asl[mb + k]);
                al[mt][1] = __float_as_uint(Asl[mb + 8 * LDPA + k]);
                al[mt][2] = __float_as_uint(Asl[mb + k + 4]);
                al[mt][3] = __float_as_uint(Asl[mb + 8 * LDPA + k + 4]);
            }
            #pragma unroll
            for (int nt = 0; nt < 4; nt++) {
                const int nb = (warp_n * 32 + nt * 8 + grp) * LDPA;
                bh[nt][0] = __float_as_uint(Bsh[nb + k]);
                bh[nt][1] = __float_as_uint(Bsh[nb + k + 4]);
                bl[nt][0] = __float_as_uint(Bsl[nb + k]);
                bl[nt][1] = __float_as_uint(Bsl[nb + k + 4]);
            }
            #pragma unroll
            for (int mt = 0; mt < 4; mt++)
                #pragma unroll
                for (int nt = 0; nt < 4; nt++) {
                    mma8(acc[mt][nt], ah[mt], bh[nt]);
                    mma8(acc[mt][nt], ah[mt], bl[nt]);
                    mma8(acc[mt][nt], al[mt], bh[nt]);
                }
        }
    }

    // epilogue
    #pragma unroll
    for (int mt = 0; mt < 4; mt++) {
        const int m = m0 + warp_m * 64 + mt * 16 + grp;
        #pragma unroll
        for (int nt = 0; nt < 4; nt++) {
            const int nl = warp_n * 32 + nt * 8 + q * 2;
            float2 v0, v1;
            v0.x = acc[mt][nt][0] + bp[nl];
            v0.y = acc[mt][nt][1] + bp[nl + 1];
            v1.x = acc[mt][nt][2] + bp[nl];
            v1.y = acc[mt][nt][3] + bp[nl + 1];
            if (MODE == 0) {
                if (n0 < CD) {
                    *(float2*)&g_q[(size_t)m * CD + n0 + nl] = v0;
                    *(float2*)&g_q[(size_t)(m + 8) * CD + n0 + nl] = v1;
                } else {
                    float2 h0, l0f, h1, l1f;
                    h0.x = tf32_rna(v0.x); l0f.x = tf32_rna(v0.x - h0.x);
                    h0.y = tf32_rna(v0.y); l0f.y = tf32_rna(v0.y - h0.y);
                    h1.x = tf32_rna(v1.x); l1f.x = tf32_rna(v1.x - h1.x);
                    h1.y = tf32_rna(v1.y); l1f.y = tf32_rna(v1.y - h1.y);
                    *(float2*)&g_kvh[(size_t)m * 128 + nl] = h0;
                    *(float2*)&g_kvl[(size_t)m * 128 + nl] = l0f;
                    *(float2*)&g_kvh[(size_t)(m + 8) * 128 + nl] = h1;
                    *(float2*)&g_kvl[(size_t)(m + 8) * 128 + nl] = l1f;
                }
            } else {
                *(float2*)&Cout[(size_t)m * CD + n0 + nl] = v0;
                *(float2*)&Cout[(size_t)(m + 8) * CD + n0 + nl] = v1;
            }
        }
    }
}

// ---------------------------------------------------------------------------
// Kernel 3: flash attention on tensor cores (R13-passing version; epilogue
// writes hi/lo split planes so gemm1 can cp.async them directly).
// ---------------------------------------------------------------------------
#define ASTAGE 17408
#define AT_PW  (2 * ASTAGE)
#define ATTN_SMEM_BYTES ((AT_PW + 8 * 16 * 72) * 4)   // 176128

__global__ __launch_bounds__(256) void attn_tc()
{
    extern __shared__ float smf[];
    const uint32_t sb = smem_u32(smf);

    const int b   = blockIdx.y;
    const int s0  = blockIdx.x * 8;
    const int tid = threadIdx.x;
    const int w   = tid >> 5;
    const int lane = tid & 31;
    const int grp = lane >> 2;
    const int q   = lane & 3;
    const int s_w = s0 + w;
    float* Pme = smf + AT_PW + w * (16 * 72);

    const float* kvh = g_kvh + (size_t)(b * CS) * 128;
    const float* kvl = g_kvl + (size_t)(b * CS) * 128;

    int pl_[16], r_[16], c_[16];
    #pragma unroll
    for (int i = 0; i < 16; i++) {
        int c = tid + i * 256;
        pl_[i] = c >> 10;
        r_[i]  = (c & 1023) >> 4;
        c_[i]  = (c & 15) << 2;
    }

    uint32_t qh[8][4], ql[8][4];
    {
        const float* qb = g_q + (size_t)(b * CS + s_w) * 1024;
        #pragma unroll
        for (int kf = 0; kf < 8; kf++) {
            float a0 = 0.125f * qb[grp * 64 + kf * 8 + q];
            float a1 = 0.125f * qb[(grp + 8) * 64 + kf * 8 + q];
            float a2 = 0.125f * qb[grp * 64 + kf * 8 + q + 4];
            float a3 = 0.125f * qb[(grp + 8) * 64 + kf * 8 + q + 4];
            split_tf32(a0, qh[kf][0], ql[kf][0]);
            split_tf32(a1, qh[kf][1], ql[kf][1]);
            split_tf32(a2, qh[kf][2], ql[kf][2]);
            split_tf32(a3, qh[kf][3], ql[kf][3]);
        }
    }

    float acc[8][4];
    #pragma unroll
    for (int nf = 0; nf < 8; nf++)
        #pragma unroll
        for (int r = 0; r < 4; r++) acc[nf][r] = 0.f;
    float m0 = -1e30f, m1 = -1e30f, l0 = 0.f, l1 = 0.f;

    const int ntile = ((s0 + 7) >> 6) + 1;

    #pragma unroll
    for (int i = 0; i < 16; i++) {
        const uint32_t dst = sb + (uint32_t)(pl_[i] * 4352 + r_[i] * 68 + c_[i]) * 4;
        const float* src = (pl_[i] & 1 ? kvl : kvh)
                         + (size_t)r_[i] * 128 + ((pl_[i] >> 1) ? 64 : 0) + c_[i];
        cp16(dst, src);
    }
    CP_COMMIT();

    for (int tt = 0; tt < ntile; tt++) {
        const int t0 = tt * 64;
        const float* stage = smf + (tt & 1) * ASTAGE;
        const float* Khi = stage;
        const float* Klo = stage + 4352;
        const float* Vhi = stage + 8704;
        const float* Vlo = stage + 13056;

        CP_WAIT(0);
        __syncthreads();

        if (tt + 1 < ntile) {
            const uint32_t sbase = sb + (uint32_t)(((tt + 1) & 1) * ASTAGE) * 4;
            const size_t gshift = (size_t)(t0 + 64) * 128;
            #pragma unroll
            for (int i = 0; i < 16; i++) {
                const uint32_t dst = sbase + (uint32_t)(pl_[i] * 4352 + r_[i] * 68 + c_[i]) * 4;
                const float* src = (pl_[i] & 1 ? kvl : kvh)
                                 + gshift + (size_t)r_[i] * 128 + ((pl_[i] >> 1) ? 64 : 0) + c_[i];
                cp16(dst, src);
            }
            CP_COMMIT();
        }

        if (t0 <= s_w) {
            float sc[8][4];
            #pragma unroll
            for (int nf = 0; nf < 8; nf++)
                #pragma unroll
                for (int r = 0; r < 4; r++) sc[nf][r] = 0.f;

            #pragma unroll
            for (int kf = 0; kf < 8; kf++) {
                #pragma unroll
                for (int nf = 0; nf < 8; nf++) {
                    const int kb = (nf * 8 + grp) * 68 + kf * 8 + q;
                    uint32_t bh[2], bl[2];
                    bh[0] = __float_as_uint(Khi[kb]);
                    bh[1] = __float_as_uint(Khi[kb + 4]);
                    bl[0] = __float_as_uint(Klo[kb]);
                    bl[1] = __float_as_uint(Klo[kb + 4]);
                    mma8(sc[nf], qh[kf], bh);
                    mma8(sc[nf], qh[kf], bl);
                    mma8(sc[nf], ql[kf], bh);
                }
            }

            if (t0 + 63 > s_w) {
                #pragma unroll
                for (int nf = 0; nf < 8; nf++) {
                    const int t = t0 + nf * 8 + 2 * q;
                    if (t > s_w)     { sc[nf][0] = -1e30f; sc[nf][2] = -1e30f; }
                    if (t + 1 > s_w) { sc[nf][1] = -1e30f; sc[nf][3] = -1e30f; }
                }
            }

            float r0 = -1e30f, r1 = -1e30f;
            #pragma unroll
            for (int nf = 0; nf < 8; nf++) {
                r0 = fmaxf(r0, fmaxf(sc[nf][0], sc[nf][1]));
                r1 = fmaxf(r1, fmaxf(sc[nf][2], sc[nf][3]));
            }
            r0 = fmaxf(r0, __shfl_xor_sync(0xffffffffu, r0, 1));
            r0 = fmaxf(r0, __shfl_xor_sync(0xffffffffu, r0, 2));
            r1 = fmaxf(r1, __shfl_xor_sync(0xffffffffu, r1, 1));
            r1 = fmaxf(r1, __shfl_xor_sync(0xffffffffu, r1, 2));
            const float mn0 = fmaxf(m0, r0), mn1 = fmaxf(m1, r1);
            const float c0 = __expf(m0 - mn0), c1 = __expf(m1 - mn1);
            m0 = mn0; m1 = mn1;

            float rs0 = 0.f, rs1 = 0.f;
            #pragma unroll
            for (int nf = 0; nf < 8; nf++) {
                float p0 = __expf(sc[nf][0] - m0);
                float p1 = __expf(sc[nf][1] - m0);
                float p2 = __expf(sc[nf][2] - m1);
                float p3 = __expf(sc[nf][3] - m1);
                rs0 += p0 + p1;
                rs1 += p2 + p3;
                *(float2*)&Pme[grp * 72 + nf * 8 + 2 * q]       = make_float2(p0, p1);
                *(float2*)&Pme[(grp + 8) * 72 + nf * 8 + 2 * q] = make_float2(p2, p3);
            }
            rs0 += __shfl_xor_sync(0xffffffffu, rs0, 1);
            rs0 += __shfl_xor_sync(0xffffffffu, rs0, 2);
            rs1 += __shfl_xor_sync(0xffffffffu, rs1, 1);
            rs1 += __shfl_xor_sync(0xffffffffu, rs1, 2);
            l0 = l0 * c0 + rs0;
            l1 = l1 * c1 + rs1;

            #pragma unroll
            for (int nf = 0; nf < 8; nf++) {
                acc[nf][0] *= c0; acc[nf][1] *= c0;
                acc[nf][2] *= c1; acc[nf][3] *= c1;
            }
            __syncwarp();

            #pragma unroll
            for (int kf = 0; kf < 8; kf++) {
                uint32_t ph[4], pl2[4];
                split_tf32(Pme[grp * 72 + kf * 8 + q],            ph[0], pl2[0]);
                split_tf32(Pme[(grp + 8) * 72 + kf * 8 + q],      ph[1], pl2[1]);
                split_tf32(Pme[grp * 72 + kf * 8 + q + 4],        ph[2], pl2[2]);
                split_tf32(Pme[(grp + 8) * 72 + kf * 8 + q + 4],  ph[3], pl2[3]);
                #pragma unroll
                for (int nf = 0; nf < 8; nf++) {
                    const int vb0 = (kf * 8 + q) * 68 + nf * 8 + grp;
                    const int vb1 = (kf * 8 + q + 4) * 68 + nf * 8 + grp;
                    uint32_t bh[2], bl[2];
                    bh[0] = __float_as_uint(Vhi[vb0]);
                    bh[1] = __float_as_uint(Vhi[vb1]);
                    bl[0] = __float_as_uint(Vlo[vb0]);
                    bl[1] = __float_as_uint(Vlo[vb1]);
                    mma8(acc[nf], ph, bh);
                    mma8(acc[nf], ph, bl);
                    mma8(acc[nf], pl2, bh);
                }
            }
        }
    }

    // ---- normalize + write PRE-SPLIT planes for gemm1 ----
    const float inv0 = 1.0f / l0, inv1 = 1.0f / l1;
    float* obh = g_aoh + (size_t)(b * CS + s_w) * 1024;
    float* obl = g_aol + (size_t)(b * CS + s_w) * 1024;
    #pragma unroll
    for (int nf = 0; nf < 8; nf++) {
        float o0 = acc[nf][0] * inv0, o1 = acc[nf][1] * inv0;
        float o2 = acc[nf][2] * inv1, o3 = acc[nf][3] * inv1;
        float2 h0, lw0, h1, lw1;
        h0.x = tf32_rna(o0); lw0.x = tf32_rna(o0 - h0.x);
        h0.y = tf32_rna(o1); lw0.y = tf32_rna(o1 - h0.y);
        h1.x = tf32_rna(o2); lw1.x = tf32_rna(o2 - h1.x);
        h1.y = tf32_rna(o3); lw1.y = tf32_rna(o3 - h1.y);
        *(float2*)&obh[grp * 64 + nf * 8 + 2 * q] = h0;
        *(float2*)&obl[grp * 64 + nf * 8 + 2 * q] = lw0;
        *(float2*)&obh[(grp + 8) * 64 + nf * 8 + 2 * q] = h1;
        *(float2*)&obl[(grp + 8) * 64 + nf * 8 + 2 * q] = lw1;
    }
}

// ---------------------------------------------------------------------------
extern "C" void kernel_launch(void* const* d_in, const int* in_sizes, int n_in,
                              void* d_out, int out_size)
{
    const float* x    = (const float*)d_in[0];
    const float* Wqkv = (const float*)d_in[1];
    const float* bqkv = (const float*)d_in[2];
    const float* Wout = (const float*)d_in[3];
    const float* bout = (const float*)d_in[4];
    float* out = (float*)d_out;

    cudaFuncSetAttribute(gemm_cp<0>, cudaFuncAttributeMaxDynamicSharedMemorySize,
                         GEMM_SMEM_BYTES);
    cudaFuncSetAttribute(gemm_cp<1>, cudaFuncAttributeMaxDynamicSharedMemorySize,
                         GEMM_SMEM_BYTES);
    cudaFuncSetAttribute(attn_tc, cudaFuncAttributeMaxDynamicSharedMemorySize,
                         ATTN_SMEM_BYTES);

    // prep: head-sum, then pre-split all GEMM operands to hi/lo tf32 planes
    prep_k<<<512, 256>>>(Wqkv, bqkv);
    prep_split_x<<<(CM * CD) / 256, 256>>>(x);
    prep_W0<<<(1152 * CD) / 256, 256>>>(Wqkv, bqkv);
    prep_Wout<<<(CD * CD) / 256, 256>>>(Wout);

    // fused q + kv_sum GEMM (cp.async, 2 CTAs/SM, single wave)
    gemm_cp<0><<<dim3(9, 32), 256, GEMM_SMEM_BYTES>>>(nullptr, nullptr);
    // causal flash attention on tensor cores
    attn_tc<<<dim3(CS / 8, CB), 256, ATTN_SMEM_BYTES>>>();
    // output projection
    gemm_cp<1><<<dim3(8, 32), 256, GEMM_SMEM_BYTES>>>(bout, out);
}

// round 16
// speedup vs baseline: 1.1663x; 1.1663x over previous
#include <cuda_runtime.h>
#include <cstdint>

// Problem constants
#define CB 2
#define CS 2048
#define CD 1024
#define CH 16
#define CHD 64
#define CM (CB*CS)   // 4096 tokens

// Scratch (allocation-free rule: __device__ globals; device-code refs only)
__device__ float g_q[(size_t)CM * CD];        // q activations (fp32)
__device__ float g_kvh[(size_t)CM * 128];     // hi tf32 of [k_sum | v_sum]
__device__ float g_kvl[(size_t)CM * 128];     // lo tf32
__device__ float g_attnout[(size_t)CM * CD];  // attention output (fp32)
__device__ float g_Wkv[128 * CD];             // head-summed K/V weights
__device__ float g_bkv[128];

// ---------------------------------------------------------------------------
// helpers
// ---------------------------------------------------------------------------
__device__ __forceinline__ uint32_t smem_u32(const void* p) {
    uint32_t a;
    asm("{ .reg .u64 t; cvta.to.shared.u64 t, %1; cvt.u32.u64 %0, t; }"
        : "=r"(a) : "l"(p));
    return a;
}
__device__ __forceinline__ float tf32_rna(float x) {
    uint32_t r;
    asm("cvt.rna.tf32.f32 %0, %1;" : "=r"(r) : "f"(x));
    return __uint_as_float(r);
}
__device__ __forceinline__ void split_tf32(float x, uint32_t& h, uint32_t& l) {
    float hf = tf32_rna(x);
    h = __float_as_uint(hf);
    l = __float_as_uint(tf32_rna(x - hf));
}
__device__ __forceinline__ void mma8(float* c, const uint32_t* a, const uint32_t* b) {
    asm volatile(
        "mma.sync.aligned.m16n8k8.row.col.f32.tf32.tf32.f32 "
        "{%0,%1,%2,%3}, {%4,%5,%6,%7}, {%8,%9}, {%0,%1,%2,%3};"
        : "+f"(c[0]), "+f"(c[1]), "+f"(c[2]), "+f"(c[3])
        : "r"(a[0]), "r"(a[1]), "r"(a[2]), "r"(a[3]), "r"(b[0]), "r"(b[1]));
}
__device__ __forceinline__ void cp16(uint32_t dst, const float* src) {
    asm volatile("cp.async.cg.shared.global [%0], [%1], 16;"
                 :: "r"(dst), "l"(src) : "memory");
}
#define CP_COMMIT() asm volatile("cp.async.commit_group;" ::: "memory")
#define CP_WAIT0()  asm volatile("cp.async.wait_group 0;" ::: "memory")

// ---------------------------------------------------------------------------
// Kernel 1: reduce Wqkv over heads -> Wk_sum (rows 0..63), Wv_sum (rows 64..127)
// ---------------------------------------------------------------------------
__global__ __launch_bounds__(256) void prep_k(const float* __restrict__ Wqkv,
                                              const float* __restrict__ bqkv)
{
    int idx = blockIdx.x * 256 + threadIdx.x;
    if (idx < 128 * 1024) {
        int r = idx >> 10;
        int c = idx & 1023;
        int rr = r & 63;
        int base = (r < 64 ? 1024 : 2048) + rr;
        float sum = 0.f;
        #pragma unroll
        for (int h = 0; h < 16; h++)
            sum += Wqkv[(size_t)(base + h * 64) * CD + c];
        g_Wkv[(size_t)r * CD + c] = sum;
    }
    if (idx < 128) {
        int rr = idx & 63;
        int base = (idx < 64 ? 1024 : 2048) + rr;
        float s = 0.f;
        #pragma unroll
        for (int h = 0; h < 16; h++)
            s += bqkv[base + h * 64];
        g_bkv[idx] = s;
    }
}

// ---------------------------------------------------------------------------
// tf32 mma.sync GEMM, double-buffered smem, ONE sync per K-tile (R13 base).
// MODE 0: full 3xTF32 (feeds attention; precision critical).
// MODE 1: 2xTF32 (drop al*bh; last GEMM, error ~2.4e-4 unamplified) —
//          also skips A-lo split/stores/loads entirely.
// Hazard proof (2-stage rotation): stores to buf[kt&1] at iter kt are ordered
// after sync#(kt-1), which all warps pass only after finishing their iter-
// (kt-2) MMA reads of that same buffer. Reads of buf[kt&1] at iter kt are
// ordered after sync#kt, i.e. after all stores. One barrier/iter suffices.
// ---------------------------------------------------------------------------
#define LDP 36
#define GSTAGE (4 * 128 * LDP)                  // floats per stage
#define GEMM_SMEM_BYTES (2 * GSTAGE * 4)        // 147456

template<int MODE>
__global__ __launch_bounds__(256) void gemm_mma(const float* __restrict__ A,
                                                const float* __restrict__ Bw,
                                                const float* __restrict__ bias,
                                                float* __restrict__ Cout)
{
    extern __shared__ float sm[];

    const int tid = threadIdx.x;
    const int wid = tid >> 5;
    const int lane = tid & 31;
    const int grp = lane >> 2;
    const int q   = lane & 3;
    const int warp_m = wid >> 2;
    const int warp_n = wid & 3;

    const int n0 = blockIdx.x * 128;
    const int m0 = blockIdx.y * 128;

    const float* Ap = (MODE == 0) ? A : g_attnout;   // device-side selection
    const float* Bp;
    const float* bp;
    if (MODE == 0 && n0 >= CD) { Bp = g_Wkv; bp = g_bkv; }
    else                       { Bp = Bw + (size_t)n0 * CD; bp = bias + n0; }
    const float* Abase = Ap + (size_t)m0 * CD;

    float acc[4][4][4];
    #pragma unroll
    for (int mt = 0; mt < 4; mt++)
        #pragma unroll
        for (int nt = 0; nt < 4; nt++)
            #pragma unroll
            for (int r = 0; r < 4; r++) acc[mt][nt][r] = 0.f;

    int rowv[4], colv[4];
    #pragma unroll
    for (int i = 0; i < 4; i++) {
        int f = tid + i * 256;
        rowv[i] = f >> 3;
        colv[i] = (f & 7) << 2;
    }

    float4 ra[4], rb[4];
    #pragma unroll
    for (int i = 0; i < 4; i++) {
        ra[i] = *(const float4*)(Abase + (size_t)rowv[i] * CD + colv[i]);
        rb[i] = *(const float4*)(Bp    + (size_t)rowv[i] * CD + colv[i]);
    }

    for (int kt = 0; kt < 32; kt++) {
        float* buf = sm + (kt & 1) * GSTAGE;
        float* Ash = buf;
        float* Asl = buf + 128 * LDP;
        float* Bsh = buf + 2 * 128 * LDP;
        float* Bsl = buf + 3 * 128 * LDP;

        #pragma unroll
        for (int i = 0; i < 4; i++) {
            const int so = rowv[i] * LDP + colv[i];
            float4 h, l;
            h.x = tf32_rna(ra[i].x);
            h.y = tf32_rna(ra[i].y);
            h.z = tf32_rna(ra[i].z);
            h.w = tf32_rna(ra[i].w);
            *(float4*)&Ash[so] = h;
            if (MODE == 0) {
                l.x = tf32_rna(ra[i].x - h.x);
                l.y = tf32_rna(ra[i].y - h.y);
                l.z = tf32_rna(ra[i].z - h.z);
                l.w = tf32_rna(ra[i].w - h.w);
                *(float4*)&Asl[so] = l;
            }
            h.x = tf32_rna(rb[i].x); l.x = tf32_rna(rb[i].x - h.x);
            h.y = tf32_rna(rb[i].y); l.y = tf32_rna(rb[i].y - h.y);
            h.z = tf32_rna(rb[i].z); l.z = tf32_rna(rb[i].z - h.z);
            h.w = tf32_rna(rb[i].w); l.w = tf32_rna(rb[i].w - h.w);
            *(float4*)&Bsh[so] = h;  *(float4*)&Bsl[so] = l;
        }
        __syncthreads();                       // the ONLY barrier per tile

        if (kt < 31) {
            const int k0 = (kt + 1) * 32;
            #pragma unroll
            for (int i = 0; i < 4; i++) {
                ra[i] = *(const float4*)(Abase + (size_t)rowv[i] * CD + k0 + colv[i]);
                rb[i] = *(const float4*)(Bp    + (size_t)rowv[i] * CD + k0 + colv[i]);
            }
        }

        #pragma unroll
        for (int ks = 0; ks < 4; ks++) {
            const int k = ks * 8 + q;
            uint32_t ah[4][4], al[4][4], bh[4][2], bl[4][2];
            #pragma unroll
            for (int mt = 0; mt < 4; mt++) {
                const int mb = (warp_m * 64 + mt * 16 + grp) * LDP;
                ah[mt][0] = __float_as_uint(Ash[mb + k]);
                ah[mt][1] = __float_as_uint(Ash[mb + 8 * LDP + k]);
                ah[mt][2] = __float_as_uint(Ash[mb + k + 4]);
                ah[mt][3] = __float_as_uint(Ash[mb + 8 * LDP + k + 4]);
                if (MODE == 0) {
                    al[mt][0] = __float_as_uint(Asl[mb + k]);
                    al[mt][1] = __float_as_uint(Asl[mb + 8 * LDP + k]);
                    al[mt][2] = __float_as_uint(Asl[mb + k + 4]);
                    al[mt][3] = __float_as_uint(Asl[mb + 8 * LDP + k + 4]);
                }
            }
            #pragma unroll
            for (int nt = 0; nt < 4; nt++) {
                const int nb = (warp_n * 32 + nt * 8 + grp) * LDP;
                bh[nt][0] = __float_as_uint(Bsh[nb + k]);
                bh[nt][1] = __float_as_uint(Bsh[nb + k + 4]);
                bl[nt][0] = __float_as_uint(Bsl[nb + k]);
                bl[nt][1] = __float_as_uint(Bsl[nb + k + 4]);
            }
            #pragma unroll
            for (int mt = 0; mt < 4; mt++)
                #pragma unroll
                for (int nt = 0; nt < 4; nt++) {
                    mma8(acc[mt][nt], ah[mt], bh[nt]);
                    mma8(acc[mt][nt], ah[mt], bl[nt]);
                    if (MODE == 0) mma8(acc[mt][nt], al[mt], bh[nt]);
                }
        }
    }

    // epilogue
    #pragma unroll
    for (int mt = 0; mt < 4; mt++) {
        const int m = m0 + warp_m * 64 + mt * 16 + grp;
        #pragma unroll
        for (int nt = 0; nt < 4; nt++) {
            const int nl = warp_n * 32 + nt * 8 + q * 2;
            float2 v0, v1;
            v0.x = acc[mt][nt][0] + bp[nl];
            v0.y = acc[mt][nt][1] + bp[nl + 1];
            v1.x = acc[mt][nt][2] + bp[nl];
            v1.y = acc[mt][nt][3] + bp[nl + 1];
            if (MODE == 0) {
                if (n0 < CD) {
                    *(float2*)&g_q[(size_t)m * CD + n0 + nl] = v0;
                    *(float2*)&g_q[(size_t)(m + 8) * CD + n0 + nl] = v1;
                } else {
                    // pre-split K/V hi/lo: every attention block reuses it
                    float2 h0, l0f, h1, l1f;
                    h0.x = tf32_rna(v0.x); l0f.x = tf32_rna(v0.x - h0.x);
                    h0.y = tf32_rna(v0.y); l0f.y = tf32_rna(v0.y - h0.y);
                    h1.x = tf32_rna(v1.x); l1f.x = tf32_rna(v1.x - h1.x);
                    h1.y = tf32_rna(v1.y); l1f.y = tf32_rna(v1.y - h1.y);
                    *(float2*)&g_kvh[(size_t)m * 128 + nl] = h0;
                    *(float2*)&g_kvl[(size_t)m * 128 + nl] = l0f;
                    *(float2*)&g_kvh[(size_t)(m + 8) * 128 + nl] = h1;
                    *(float2*)&g_kvl[(size_t)(m + 8) * 128 + nl] = l1f;
                }
            } else {
                *(float2*)&Cout[(size_t)m * CD + n0 + nl] = v0;
                *(float2*)&Cout[(size_t)(m + 8) * CD + n0 + nl] = v1;
            }
        }
    }
}

// ---------------------------------------------------------------------------
// Kernel 3: flash attention on tensor cores (R13 base). QK full 3xTF32;
// PV now 2 MMAs: P as single tf32 (residual ~2^-12, unamplified), V hi+lo.
// K/V pre-split in global; cp.async double-buffered smem, one sync per tile.
// ---------------------------------------------------------------------------
#define ASTAGE 17408
#define AT_PW  (2 * ASTAGE)
#define ATTN_SMEM_BYTES ((AT_PW + 8 * 16 * 72) * 4)   // 176128

__global__ __launch_bounds__(256) void attn_tc()
{
    extern __shared__ float smf[];
    const uint32_t sb = smem_u32(smf);

    const int b   = blockIdx.y;
    const int s0  = blockIdx.x * 8;
    const int tid = threadIdx.x;
    const int w   = tid >> 5;
    const int lane = tid & 31;
    const int grp = lane >> 2;
    const int q   = lane & 3;
    const int s_w = s0 + w;
    float* Pme = smf + AT_PW + w * (16 * 72);

    const float* kvh = g_kvh + (size_t)(b * CS) * 128;
    const float* kvl = g_kvl + (size_t)(b * CS) * 128;

    int pl_[16], r_[16], c_[16];
    #pragma unroll
    for (int i = 0; i < 16; i++) {
        int c = tid + i * 256;
        pl_[i] = c >> 10;
        r_[i]  = (c & 1023) >> 4;
        c_[i]  = (c & 15) << 2;
    }

    uint32_t qh[8][4], ql[8][4];
    {
        const float* qb = g_q + (size_t)(b * CS + s_w) * 1024;
        #pragma unroll
        for (int kf = 0; kf < 8; kf++) {
            float a0 = 0.125f * qb[grp * 64 + kf * 8 + q];
            float a1 = 0.125f * qb[(grp + 8) * 64 + kf * 8 + q];
            float a2 = 0.125f * qb[grp * 64 + kf * 8 + q + 4];
            float a3 = 0.125f * qb[(grp + 8) * 64 + kf * 8 + q + 4];
            split_tf32(a0, qh[kf][0], ql[kf][0]);
            split_tf32(a1, qh[kf][1], ql[kf][1]);
            split_tf32(a2, qh[kf][2], ql[kf][2]);
            split_tf32(a3, qh[kf][3], ql[kf][3]);
        }
    }

    float acc[8][4];
    #pragma unroll
    for (int nf = 0; nf < 8; nf++)
        #pragma unroll
        for (int r = 0; r < 4; r++) acc[nf][r] = 0.f;
    float m0 = -1e30f, m1 = -1e30f, l0 = 0.f, l1 = 0.f;

    const int ntile = ((s0 + 7) >> 6) + 1;

    #pragma unroll
    for (int i = 0; i < 16; i++) {
        const uint32_t dst = sb + (uint32_t)(pl_[i] * 4352 + r_[i] * 68 + c_[i]) * 4;
        const float* src = (pl_[i] & 1 ? kvl : kvh)
                         + (size_t)r_[i] * 128 + ((pl_[i] >> 1) ? 64 : 0) + c_[i];
        cp16(dst, src);
    }
    CP_COMMIT();

    for (int tt = 0; tt < ntile; tt++) {
        const int t0 = tt * 64;
        const float* stage = smf + (tt & 1) * ASTAGE;
        const float* Khi = stage;
        const float* Klo = stage + 4352;
        const float* Vhi = stage + 8704;
        const float* Vlo = stage + 13056;

        CP_WAIT0();
        __syncthreads();

        if (tt + 1 < ntile) {
            const uint32_t sbase = sb + (uint32_t)(((tt + 1) & 1) * ASTAGE) * 4;
            const size_t gshift = (size_t)(t0 + 64) * 128;
            #pragma unroll
            for (int i = 0; i < 16; i++) {
                const uint32_t dst = sbase + (uint32_t)(pl_[i] * 4352 + r_[i] * 68 + c_[i]) * 4;
                const float* src = (pl_[i] & 1 ? kvl : kvh)
                                 + gshift + (size_t)r_[i] * 128 + ((pl_[i] >> 1) ? 64 : 0) + c_[i];
                cp16(dst, src);
            }
            CP_COMMIT();
        }

        if (t0 <= s_w) {
            // ---- QK^T (full 3xTF32) ----
            float sc[8][4];
            #pragma unroll
            for (int nf = 0; nf < 8; nf++)
                #pragma unroll
                for (int r = 0; r < 4; r++) sc[nf][r] = 0.f;

            #pragma unroll
            for (int kf = 0; kf < 8; kf++) {
                #pragma unroll
                for (int nf = 0; nf < 8; nf++) {
                    const int kb = (nf * 8 + grp) * 68 + kf * 8 + q;
                    uint32_t bh[2], bl[2];
                    bh[0] = __float_as_uint(Khi[kb]);
                    bh[1] = __float_as_uint(Khi[kb + 4]);
                    bl[0] = __float_as_uint(Klo[kb]);
                    bl[1] = __float_as_uint(Klo[kb + 4]);
                    mma8(sc[nf], qh[kf], bh);
                    mma8(sc[nf], qh[kf], bl);
                    mma8(sc[nf], ql[kf], bh);
                }
            }

            if (t0 + 63 > s_w) {
                #pragma unroll
                for (int nf = 0; nf < 8; nf++) {
                    const int t = t0 + nf * 8 + 2 * q;
                    if (t > s_w)     { sc[nf][0] = -1e30f; sc[nf][2] = -1e30f; }
                    if (t + 1 > s_w) { sc[nf][1] = -1e30f; sc[nf][3] = -1e30f; }
                }
            }

            float r0 = -1e30f, r1 = -1e30f;
            #pragma unroll
            for (int nf = 0; nf < 8; nf++) {
                r0 = fmaxf(r0, fmaxf(sc[nf][0], sc[nf][1]));
                r1 = fmaxf(r1, fmaxf(sc[nf][2], sc[nf][3]));
            }
            r0 = fmaxf(r0, __shfl_xor_sync(0xffffffffu, r0, 1));
            r0 = fmaxf(r0, __shfl_xor_sync(0xffffffffu, r0, 2));
            r1 = fmaxf(r1, __shfl_xor_sync(0xffffffffu, r1, 1));
            r1 = fmaxf(r1, __shfl_xor_sync(0xffffffffu, r1, 2));
            const float mn0 = fmaxf(m0, r0), mn1 = fmaxf(m1, r1);
            const float c0 = __expf(m0 - mn0), c1 = __expf(m1 - mn1);
            m0 = mn0; m1 = mn1;

            float rs0 = 0.f, rs1 = 0.f;
            #pragma unroll
            for (int nf = 0; nf < 8; nf++) {
                float p0 = __expf(sc[nf][0] - m0);
                float p1 = __expf(sc[nf][1] - m0);
                float p2 = __expf(sc[nf][2] - m1);
                float p3 = __expf(sc[nf][3] - m1);
                rs0 += p0 + p1;
                rs1 += p2 + p3;
                *(float2*)&Pme[grp * 72 + nf * 8 + 2 * q]       = make_float2(p0, p1);
                *(float2*)&Pme[(grp + 8) * 72 + nf * 8 + 2 * q] = make_float2(p2, p3);
            }
            rs0 += __shfl_xor_sync(0xffffffffu, rs0, 1);
            rs0 += __shfl_xor_sync(0xffffffffu, rs0, 2);
            rs1 += __shfl_xor_sync(0xffffffffu, rs1, 1);
            rs1 += __shfl_xor_sync(0xffffffffu, rs1, 2);
            l0 = l0 * c0 + rs0;
            l1 = l1 * c1 + rs1;

            #pragma unroll
            for (int nf = 0; nf < 8; nf++) {
                acc[nf][0] *= c0; acc[nf][1] *= c0;
                acc[nf][2] *= c1; acc[nf][3] *= c1;
            }
            __syncwarp();

            // ---- PV: 2 MMAs (P single tf32; V hi+lo) ----
            #pragma unroll
            for (int kf = 0; kf < 8; kf++) {
                uint32_t ph[4];
                ph[0] = __float_as_uint(tf32_rna(Pme[grp * 72 + kf * 8 + q]));
                ph[1] = __float_as_uint(tf32_rna(Pme[(grp + 8) * 72 + kf * 8 + q]));
                ph[2] = __float_as_uint(tf32_rna(Pme[grp * 72 + kf * 8 + q + 4]));
                ph[3] = __float_as_uint(tf32_rna(Pme[(grp + 8) * 72 + kf * 8 + q + 4]));
                #pragma unroll
                for (int nf = 0; nf < 8; nf++) {
                    const int vb0 = (kf * 8 + q) * 68 + nf * 8 + grp;
                    const int vb1 = (kf * 8 + q + 4) * 68 + nf * 8 + grp;
                    uint32_t bh[2], bl[2];
                    bh[0] = __float_as_uint(Vhi[vb0]);
                    bh[1] = __float_as_uint(Vhi[vb1]);
                    bl[0] = __float_as_uint(Vlo[vb0]);
                    bl[1] = __float_as_uint(Vlo[vb1]);
                    mma8(acc[nf], ph, bh);
                    mma8(acc[nf], ph, bl);
                }
            }
        }
    }

    // ---- normalize + write ----
    const float inv0 = 1.0f / l0, inv1 = 1.0f / l1;
    float* ob = g_attnout + (size_t)(b * CS + s_w) * 1024;
    #pragma unroll
    for (int nf = 0; nf < 8; nf++) {
        *(float2*)&ob[grp * 64 + nf * 8 + 2 * q] =
            make_float2(acc[nf][0] * inv0, acc[nf][1] * inv0);
        *(float2*)&ob[(grp + 8) * 64 + nf * 8 + 2 * q] =
            make_float2(acc[nf][2] * inv1, acc[nf][3] * inv1);
    }
}

// ---------------------------------------------------------------------------
extern "C" void kernel_launch(void* const* d_in, const int* in_sizes, int n_in,
                              void* d_out, int out_size)
{
    const float* x    = (const float*)d_in[0];
    const float* Wqkv = (const float*)d_in[1];
    const float* bqkv = (const float*)d_in[2];
    const float* Wout = (const float*)d_in[3];
    const float* bout = (const float*)d_in[4];
    float* out = (float*)d_out;

    cudaFuncSetAttribute(gemm_mma<0>, cudaFuncAttributeMaxDynamicSharedMemorySize,
                         GEMM_SMEM_BYTES);
    cudaFuncSetAttribute(gemm_mma<1>, cudaFuncAttributeMaxDynamicSharedMemorySize,
                         GEMM_SMEM_BYTES);
    cudaFuncSetAttribute(attn_tc, cudaFuncAttributeMaxDynamicSharedMemorySize,
                         ATTN_SMEM_BYTES);

    // 1) head-sum the K/V weights+biases (linearity of the head reduction)
    prep_k<<<512, 256>>>(Wqkv, bqkv);
    // 2) fused q + kv_sum GEMM (3xTF32; kv written pre-split hi/lo)
    gemm_mma<0><<<dim3(9, 32), 256, GEMM_SMEM_BYTES>>>(x, Wqkv, bqkv, nullptr);
    // 3) causal flash attention (QK 3xTF32, PV 2xTF32)
    attn_tc<<<dim3(CS / 8, CB), 256, ATTN_SMEM_BYTES>>>();
    // 4) output projection (2xTF32)
    gemm_mma<1><<<dim3(8, 32), 256, GEMM_SMEM_BYTES>>>(nullptr, Wout, bout, out);
}

// round 17
// speedup vs baseline: 1.3540x; 1.1609x over previous
#include <cuda_runtime.h>
#include <cstdint>

// Problem constants
#define CB 2
#define CS 2048
#define CD 1024
#define CH 16
#define CHD 64
#define CM (CB*CS)   // 4096 tokens

// Scratch (allocation-free rule: __device__ globals; device-code refs only)
__device__ float g_q[(size_t)CM * CD];        // q activations (fp32)
__device__ float g_kvh[(size_t)CM * 128];     // hi tf32 of [k_sum | v_sum]
__device__ float g_kvl[(size_t)CM * 128];     // lo tf32
__device__ float g_attnout[(size_t)CM * CD];  // attention output (fp32)
__device__ float g_Wkv[128 * CD];             // head-summed K/V weights
__device__ float g_bkv[128];

// ---------------------------------------------------------------------------
// helpers
// ---------------------------------------------------------------------------
__device__ __forceinline__ uint32_t smem_u32(const void* p) {
    uint32_t a;
    asm("{ .reg .u64 t; cvta.to.shared.u64 t, %1; cvt.u32.u64 %0, t; }"
        : "=r"(a) : "l"(p));
    return a;
}
__device__ __forceinline__ float tf32_rna(float x) {
    uint32_t r;
    asm("cvt.rna.tf32.f32 %0, %1;" : "=r"(r) : "f"(x));
    return __uint_as_float(r);
}
__device__ __forceinline__ void mma8(float* c, const uint32_t* a, const uint32_t* b) {
    asm volatile(
        "mma.sync.aligned.m16n8k8.row.col.f32.tf32.tf32.f32 "
        "{%0,%1,%2,%3}, {%4,%5,%6,%7}, {%8,%9}, {%0,%1,%2,%3};"
        : "+f"(c[0]), "+f"(c[1]), "+f"(c[2]), "+f"(c[3])
        : "r"(a[0]), "r"(a[1]), "r"(a[2]), "r"(a[3]), "r"(b[0]), "r"(b[1]));
}
__device__ __forceinline__ void cp16(uint32_t dst, const float* src) {
    asm volatile("cp.async.cg.shared.global [%0], [%1], 16;"
                 :: "r"(dst), "l"(src) : "memory");
}
#define CP_COMMIT() asm volatile("cp.async.commit_group;" ::: "memory")
#define CP_WAIT0()  asm volatile("cp.async.wait_group 0;" ::: "memory")

// ---------------------------------------------------------------------------
// Kernel 1: reduce Wqkv over heads -> Wk_sum (rows 0..63), Wv_sum (rows 64..127)
// ---------------------------------------------------------------------------
__global__ __launch_bounds__(256) void prep_k(const float* __restrict__ Wqkv,
                                              const float* __restrict__ bqkv)
{
    int idx = blockIdx.x * 256 + threadIdx.x;
    if (idx < 128 * 1024) {
        int r = idx >> 10;
        int c = idx & 1023;
        int rr = r & 63;
        int base = (r < 64 ? 1024 : 2048) + rr;
        float sum = 0.f;
        #pragma unroll
        for (int h = 0; h < 16; h++)
            sum += Wqkv[(size_t)(base + h * 64) * CD + c];
        g_Wkv[(size_t)r * CD + c] = sum;
    }
    if (idx < 128) {
        int rr = idx & 63;
        int base = (idx < 64 ? 1024 : 2048) + rr;
        float s = 0.f;
        #pragma unroll
        for (int h = 0; h < 16; h++)
            s += bqkv[base + h * 64];
        g_bkv[idx] = s;
    }
}

// ---------------------------------------------------------------------------
// tf32 mma.sync GEMM, double-buffered smem, ONE sync per K-tile (R16, passing).
// MODE 0: full 3xTF32 (feeds attention). MODE 1: 2xTF32 (last GEMM).
// ---------------------------------------------------------------------------
#define LDP 36
#define GSTAGE (4 * 128 * LDP)
#define GEMM_SMEM_BYTES (2 * GSTAGE * 4)        // 147456

template<int MODE>
__global__ __launch_bounds__(256) void gemm_mma(const float* __restrict__ A,
                                                const float* __restrict__ Bw,
                                                const float* __restrict__ bias,
                                                float* __restrict__ Cout)
{
    extern __shared__ float sm[];

    const int tid = threadIdx.x;
    const int wid = tid >> 5;
    const int lane = tid & 31;
    const int grp = lane >> 2;
    const int q   = lane & 3;
    const int warp_m = wid >> 2;
    const int warp_n = wid & 3;

    const int n0 = blockIdx.x * 128;
    const int m0 = blockIdx.y * 128;

    const float* Ap = (MODE == 0) ? A : g_attnout;
    const float* Bp;
    const float* bp;
    if (MODE == 0 && n0 >= CD) { Bp = g_Wkv; bp = g_bkv; }
    else                       { Bp = Bw + (size_t)n0 * CD; bp = bias + n0; }
    const float* Abase = Ap + (size_t)m0 * CD;

    float acc[4][4][4];
    #pragma unroll
    for (int mt = 0; mt < 4; mt++)
        #pragma unroll
        for (int nt = 0; nt < 4; nt++)
            #pragma unroll
            for (int r = 0; r < 4; r++) acc[mt][nt][r] = 0.f;

    int rowv[4], colv[4];
    #pragma unroll
    for (int i = 0; i < 4; i++) {
        int f = tid + i * 256;
        rowv[i] = f >> 3;
        colv[i] = (f & 7) << 2;
    }

    float4 ra[4], rb[4];
    #pragma unroll
    for (int i = 0; i < 4; i++) {
        ra[i] = *(const float4*)(Abase + (size_t)rowv[i] * CD + colv[i]);
        rb[i] = *(const float4*)(Bp    + (size_t)rowv[i] * CD + colv[i]);
    }

    for (int kt = 0; kt < 32; kt++) {
        float* buf = sm + (kt & 1) * GSTAGE;
        float* Ash = buf;
        float* Asl = buf + 128 * LDP;
        float* Bsh = buf + 2 * 128 * LDP;
        float* Bsl = buf + 3 * 128 * LDP;

        #pragma unroll
        for (int i = 0; i < 4; i++) {
            const int so = rowv[i] * LDP + colv[i];
            float4 h, l;
            h.x = tf32_rna(ra[i].x);
            h.y = tf32_rna(ra[i].y);
            h.z = tf32_rna(ra[i].z);
            h.w = tf32_rna(ra[i].w);
            *(float4*)&Ash[so] = h;
            if (MODE == 0) {
                l.x = tf32_rna(ra[i].x - h.x);
                l.y = tf32_rna(ra[i].y - h.y);
                l.z = tf32_rna(ra[i].z - h.z);
                l.w = tf32_rna(ra[i].w - h.w);
                *(float4*)&Asl[so] = l;
            }
            h.x = tf32_rna(rb[i].x); l.x = tf32_rna(rb[i].x - h.x);
            h.y = tf32_rna(rb[i].y); l.y = tf32_rna(rb[i].y - h.y);
            h.z = tf32_rna(rb[i].z); l.z = tf32_rna(rb[i].z - h.z);
            h.w = tf32_rna(rb[i].w); l.w = tf32_rna(rb[i].w - h.w);
            *(float4*)&Bsh[so] = h;  *(float4*)&Bsl[so] = l;
        }
        __syncthreads();

        if (kt < 31) {
            const int k0 = (kt + 1) * 32;
            #pragma unroll
            for (int i = 0; i < 4; i++) {
                ra[i] = *(const float4*)(Abase + (size_t)rowv[i] * CD + k0 + colv[i]);
                rb[i] = *(const float4*)(Bp    + (size_t)rowv[i] * CD + k0 + colv[i]);
            }
        }

        #pragma unroll
        for (int ks = 0; ks < 4; ks++) {
            const int k = ks * 8 + q;
            uint32_t ah[4][4], al[4][4], bh[4][2], bl[4][2];
            #pragma unroll
            for (int mt = 0; mt < 4; mt++) {
                const int mb = (warp_m * 64 + mt * 16 + grp) * LDP;
                ah[mt][0] = __float_as_uint(Ash[mb + k]);
                ah[mt][1] = __float_as_uint(Ash[mb + 8 * LDP + k]);
                ah[mt][2] = __float_as_uint(Ash[mb + k + 4]);
                ah[mt][3] = __float_as_uint(Ash[mb + 8 * LDP + k + 4]);
                if (MODE == 0) {
                    al[mt][0] = __float_as_uint(Asl[mb + k]);
                    al[mt][1] = __float_as_uint(Asl[mb + 8 * LDP + k]);
                    al[mt][2] = __float_as_uint(Asl[mb + k + 4]);
                    al[mt][3] = __float_as_uint(Asl[mb + 8 * LDP + k + 4]);
                }
            }
            #pragma unroll
            for (int nt = 0; nt < 4; nt++) {
                const int nb = (warp_n * 32 + nt * 8 + grp) * LDP;
                bh[nt][0] = __float_as_uint(Bsh[nb + k]);
                bh[nt][1] = __float_as_uint(Bsh[nb + k + 4]);
                bl[nt][0] = __float_as_uint(Bsl[nb + k]);
                bl[nt][1] = __float_as_uint(Bsl[nb + k + 4]);
            }
            #pragma unroll
            for (int mt = 0; mt < 4; mt++)
                #pragma unroll
                for (int nt = 0; nt < 4; nt++) {
                    mma8(acc[mt][nt], ah[mt], bh[nt]);
                    mma8(acc[mt][nt], ah[mt], bl[nt]);
                    if (MODE == 0) mma8(acc[mt][nt], al[mt], bh[nt]);
                }
        }
    }

    #pragma unroll
    for (int mt = 0; mt < 4; mt++) {
        const int m = m0 + warp_m * 64 + mt * 16 + grp;
        #pragma unroll
        for (int nt = 0; nt < 4; nt++) {
            const int nl = warp_n * 32 + nt * 8 + q * 2;
            float2 v0, v1;
            v0.x = acc[mt][nt][0] + bp[nl];
            v0.y = acc[mt][nt][1] + bp[nl + 1];
            v1.x = acc[mt][nt][2] + bp[nl];
            v1.y = acc[mt][nt][3] + bp[nl + 1];
            if (MODE == 0) {
                if (n0 < CD) {
                    *(float2*)&g_q[(size_t)m * CD + n0 + nl] = v0;
                    *(float2*)&g_q[(size_t)(m + 8) * CD + n0 + nl] = v1;
                } else {
                    float2 h0, l0f, h1, l1f;
                    h0.x = tf32_rna(v0.x); l0f.x = tf32_rna(v0.x - h0.x);
                    h0.y = tf32_rna(v0.y); l0f.y = tf32_rna(v0.y - h0.y);
                    h1.x = tf32_rna(v1.x); l1f.x = tf32_rna(v1.x - h1.x);
                    h1.y = tf32_rna(v1.y); l1f.y = tf32_rna(v1.y - h1.y);
                    *(float2*)&g_kvh[(size_t)m * 128 + nl] = h0;
                    *(float2*)&g_kvl[(size_t)m * 128 + nl] = l0f;
                    *(float2*)&g_kvh[(size_t)(m + 8) * 128 + nl] = h1;
                    *(float2*)&g_kvl[(size_t)(m + 8) * 128 + nl] = l1f;
                }
            } else {
                *(float2*)&Cout[(size_t)m * CD + n0 + nl] = v0;
                *(float2*)&Cout[(size_t)(m + 8) * CD + n0 + nl] = v1;
            }
        }
    }
}

// ---------------------------------------------------------------------------
// Kernel 3: flash attention on tensor cores, v2:
//  - QK: Q single tf32 x K hi/lo  (2 MMAs)
//  - PV: P single tf32 x V hi     (1 MMA)  [P>=0, errors common-mode cancel]
//  - P relayout C-frag -> A-frag via quad (width-4) shuffles: no smem buffer
//  - 3 smem planes/stage (Khi,Klo,Vhi) = 52.2KB; x2 stages = 104.4KB
//    -> 2 CTAs/SM (__launch_bounds__(256,2))
// ---------------------------------------------------------------------------
#define APLN 4352                  // floats per plane (64*68)
#define ASTAGE (3 * APLN)          // 13056 floats per stage
#define ATTN_SMEM_BYTES (2 * ASTAGE * 4)   // 104448

__global__ __launch_bounds__(256, 2) void attn_tc()
{
    extern __shared__ float smf[];
    const uint32_t sb = smem_u32(smf);

    const int b   = blockIdx.y;
    const int s0  = blockIdx.x * 8;
    const int tid = threadIdx.x;
    const int w   = tid >> 5;
    const int lane = tid & 31;
    const int grp = lane >> 2;
    const int q   = lane & 3;
    const int s_w = s0 + w;

    const float* kvh = g_kvh + (size_t)(b * CS) * 128;
    const float* kvl = g_kvl + (size_t)(b * CS) * 128;

    // ---- Q A-fragments (scaled, single tf32) ----
    uint32_t qh[8][4];
    {
        const float* qb = g_q + (size_t)(b * CS + s_w) * 1024;
        #pragma unroll
        for (int kf = 0; kf < 8; kf++) {
            qh[kf][0] = __float_as_uint(tf32_rna(0.125f * qb[grp * 64 + kf * 8 + q]));
            qh[kf][1] = __float_as_uint(tf32_rna(0.125f * qb[(grp + 8) * 64 + kf * 8 + q]));
            qh[kf][2] = __float_as_uint(tf32_rna(0.125f * qb[grp * 64 + kf * 8 + q + 4]));
            qh[kf][3] = __float_as_uint(tf32_rna(0.125f * qb[(grp + 8) * 64 + kf * 8 + q + 4]));
        }
    }

    float acc[8][4];
    #pragma unroll
    for (int nf = 0; nf < 8; nf++)
        #pragma unroll
        for (int r = 0; r < 4; r++) acc[nf][r] = 0.f;
    float m0 = -1e30f, m1 = -1e30f, l0 = 0.f, l1 = 0.f;

    const int ntile = ((s0 + 7) >> 6) + 1;

    // issue tile 0: 3 planes x 64 rows x 64 cols = 12288 floats = 12 x 16B/thread
    #pragma unroll
    for (int i = 0; i < 12; i++) {
        const int c = tid + i * 256;
        const int pl = c >> 10;               // 0:Khi 1:Klo 2:Vhi
        const int r  = (c & 1023) >> 4;
        const int c4 = (c & 15) << 2;
        const float* src = (pl == 1 ? kvl : kvh) + (size_t)r * 128
                         + (pl == 2 ? 64 : 0) + c4;
        cp16(sb + (uint32_t)(pl * APLN + r * 68 + c4) * 4, src);
    }
    CP_COMMIT();

    for (int tt = 0; tt < ntile; tt++) {
        const int t0 = tt * 64;
        const float* stage = smf + (tt & 1) * ASTAGE;
        const float* Khi = stage;
        const float* Klo = stage + APLN;
        const float* Vhi = stage + 2 * APLN;

        CP_WAIT0();
        __syncthreads();

        if (tt + 1 < ntile) {
            const uint32_t sbase = sb + (uint32_t)(((tt + 1) & 1) * ASTAGE) * 4;
            const size_t gshift = (size_t)(t0 + 64) * 128;
            #pragma unroll
            for (int i = 0; i < 12; i++) {
                const int c = tid + i * 256;
                const int pl = c >> 10;
                const int r  = (c & 1023) >> 4;
                const int c4 = (c & 15) << 2;
                const float* src = (pl == 1 ? kvl : kvh) + gshift + (size_t)r * 128
                                 + (pl == 2 ? 64 : 0) + c4;
                cp16(sbase + (uint32_t)(pl * APLN + r * 68 + c4) * 4, src);
            }
            CP_COMMIT();
        }

        if (t0 <= s_w) {
            // ---- QK^T: q single x K hi/lo (2 MMAs) ----
            float sc[8][4];
            #pragma unroll
            for (int nf = 0; nf < 8; nf++)
                #pragma unroll
                for (int r = 0; r < 4; r++) sc[nf][r] = 0.f;

            #pragma unroll
            for (int kf = 0; kf < 8; kf++) {
                #pragma unroll
                for (int nf = 0; nf < 8; nf++) {
                    const int kb = (nf * 8 + grp) * 68 + kf * 8 + q;
                    uint32_t bh[2], bl[2];
                    bh[0] = __float_as_uint(Khi[kb]);
                    bh[1] = __float_as_uint(Khi[kb + 4]);
                    bl[0] = __float_as_uint(Klo[kb]);
                    bl[1] = __float_as_uint(Klo[kb + 4]);
                    mma8(sc[nf], qh[kf], bh);
                    mma8(sc[nf], qh[kf], bl);
                }
            }

            // ---- causal mask (warp-uniform, column-only) ----
            if (t0 + 63 > s_w) {
                #pragma unroll
                for (int nf = 0; nf < 8; nf++) {
                    const int t = t0 + nf * 8 + 2 * q;
                    if (t > s_w)     { sc[nf][0] = -1e30f; sc[nf][2] = -1e30f; }
                    if (t + 1 > s_w) { sc[nf][1] = -1e30f; sc[nf][3] = -1e30f; }
                }
            }

            // ---- online softmax (p computed in place into sc) ----
            float r0 = -1e30f, r1 = -1e30f;
            #pragma unroll
            for (int nf = 0; nf < 8; nf++) {
                r0 = fmaxf(r0, fmaxf(sc[nf][0], sc[nf][1]));
                r1 = fmaxf(r1, fmaxf(sc[nf][2], sc[nf][3]));
            }
            r0 = fmaxf(r0, __shfl_xor_sync(0xffffffffu, r0, 1));
            r0 = fmaxf(r0, __shfl_xor_sync(0xffffffffu, r0, 2));
            r1 = fmaxf(r1, __shfl_xor_sync(0xffffffffu, r1, 1));
            r1 = fmaxf(r1, __shfl_xor_sync(0xffffffffu, r1, 2));
            const float mn0 = fmaxf(m0, r0), mn1 = fmaxf(m1, r1);
            const float c0 = __expf(m0 - mn0), c1 = __expf(m1 - mn1);
            m0 = mn0; m1 = mn1;

            float rs0 = 0.f, rs1 = 0.f;
            #pragma unroll
            for (int nf = 0; nf < 8; nf++) {
                sc[nf][0] = __expf(sc[nf][0] - m0);
                sc[nf][1] = __expf(sc[nf][1] - m0);
                sc[nf][2] = __expf(sc[nf][2] - m1);
                sc[nf][3] = __expf(sc[nf][3] - m1);
                rs0 += sc[nf][0] + sc[nf][1];
                rs1 += sc[nf][2] + sc[nf][3];
            }
            rs0 += __shfl_xor_sync(0xffffffffu, rs0, 1);
            rs0 += __shfl_xor_sync(0xffffffffu, rs0, 2);
            rs1 += __shfl_xor_sync(0xffffffffu, rs1, 1);
            rs1 += __shfl_xor_sync(0xffffffffu, rs1, 2);
            l0 = l0 * c0 + rs0;
            l1 = l1 * c1 + rs1;

            #pragma unroll
            for (int nf = 0; nf < 8; nf++) {
                acc[nf][0] *= c0; acc[nf][1] *= c0;
                acc[nf][2] *= c1; acc[nf][3] *= c1;
            }

            // ---- PV: P relayout via quad shuffles, 1 MMA with V hi ----
            // A-frag for k-block kf needs P cols kf*8+{q,q+4}, rows {grp,grp+8}.
            // Col c is held by quad-lane c>>1 in reg parity c&1 of sc[kf].
            const int sl0 = q >> 1;            // source lane (within quad) for col q
            const int sl1 = sl0 + 2;           // for col q+4 (same parity)
            const bool odd = (q & 1);
            #pragma unroll
            for (int kf = 0; kf < 8; kf++) {
                float e0 = __shfl_sync(0xffffffffu, sc[kf][0], sl0, 4);
                float o0 = __shfl_sync(0xffffffffu, sc[kf][1], sl0, 4);
                float e1 = __shfl_sync(0xffffffffu, sc[kf][2], sl0, 4);
                float o1 = __shfl_sync(0xffffffffu, sc[kf][3], sl0, 4);
                float e2 = __shfl_sync(0xffffffffu, sc[kf][0], sl1, 4);
                float o2 = __shfl_sync(0xffffffffu, sc[kf][1], sl1, 4);
                float e3 = __shfl_sync(0xffffffffu, sc[kf][2], sl1, 4);
                float o3 = __shfl_sync(0xffffffffu, sc[kf][3], sl1, 4);
                uint32_t ph[4];
                ph[0] = __float_as_uint(tf32_rna(odd ? o0 : e0));
                ph[1] = __float_as_uint(tf32_rna(odd ? o1 : e1));
                ph[2] = __float_as_uint(tf32_rna(odd ? o2 : e2));
                ph[3] = __float_as_uint(tf32_rna(odd ? o3 : e3));
                #pragma unroll
                for (int nf = 0; nf < 8; nf++) {
                    uint32_t bh[2];
                    bh[0] = __float_as_uint(Vhi[(kf * 8 + q) * 68 + nf * 8 + grp]);
                    bh[1] = __float_as_uint(Vhi[(kf * 8 + q + 4) * 68 + nf * 8 + grp]);
                    mma8(acc[nf], ph, bh);
                }
            }
        }
    }

    // ---- normalize + write ----
    const float inv0 = 1.0f / l0, inv1 = 1.0f / l1;
    float* ob = g_attnout + (size_t)(b * CS + s_w) * 1024;
    #pragma unroll
    for (int nf = 0; nf < 8; nf++) {
        *(float2*)&ob[grp * 64 + nf * 8 + 2 * q] =
            make_float2(acc[nf][0] * inv0, acc[nf][1] * inv0);
        *(float2*)&ob[(grp + 8) * 64 + nf * 8 + 2 * q] =
            make_float2(acc[nf][2] * inv1, acc[nf][3] * inv1);
    }
}

// ---------------------------------------------------------------------------
extern "C" void kernel_launch(void* const* d_in, const int* in_sizes, int n_in,
                              void* d_out, int out_size)
{
    const float* x    = (const float*)d_in[0];
    const float* Wqkv = (const float*)d_in[1];
    const float* bqkv = (const float*)d_in[2];
    const float* Wout = (const float*)d_in[3];
    const float* bout = (const float*)d_in[4];
    float* out = (float*)d_out;

    cudaFuncSetAttribute(gemm_mma<0>, cudaFuncAttributeMaxDynamicSharedMemorySize,
                         GEMM_SMEM_BYTES);
    cudaFuncSetAttribute(gemm_mma<1>, cudaFuncAttributeMaxDynamicSharedMemorySize,
                         GEMM_SMEM_BYTES);
    cudaFuncSetAttribute(attn_tc, cudaFuncAttributeMaxDynamicSharedMemorySize,
                         ATTN_SMEM_BYTES);

    // 1) head-sum the K/V weights+biases (linearity of the head reduction)
    prep_k<<<512, 256>>>(Wqkv, bqkv);
    // 2) fused q + kv_sum GEMM (3xTF32; kv written pre-split hi/lo)
    gemm_mma<0><<<dim3(9, 32), 256, GEMM_SMEM_BYTES>>>(x, Wqkv, bqkv, nullptr);
    // 3) causal flash attention (QK 2-mma, PV 1-mma, 2 CTAs/SM)
    attn_tc<<<dim3(CS / 8, CB), 256, ATTN_SMEM_BYTES>>>();
    // 4) output projection (2xTF32)
    gemm_mma<1><<<dim3(8, 32), 256, GEMM_SMEM_BYTES>>>(nullptr, Wout, bout, out);
}